// round 3
// baseline (speedup 1.0000x reference)
#include <cuda_runtime.h>

// BetterBot round-3: 2 tokens/lane, 4 samples/warp, fused softmax (no max-sub,
// no score array), prep-kernel-packed weights + layer-0 qkv table, ex2.approx
// with 0.5*log2e folded into q weights.

#define TPB 256
#define NW  8
#define SPB 32   // samples per block (4 per warp)

typedef unsigned long long u64;
typedef ulonglong2 u64x2;

__device__ __forceinline__ u64 pk2(float lo, float hi) {
    u64 r; asm("mov.b64 %0,{%1,%2};" : "=l"(r) : "f"(lo), "f"(hi)); return r;
}
__device__ __forceinline__ void upk2(u64 v, float &lo, float &hi) {
    asm("mov.b64 {%0,%1},%2;" : "=f"(lo), "=f"(hi) : "l"(v));
}
__device__ __forceinline__ u64 ffma2(u64 a, u64 b, u64 c) {
    u64 d; asm("fma.rn.f32x2 %0,%1,%2,%3;" : "=l"(d) : "l"(a), "l"(b), "l"(c)); return d;
}
__device__ __forceinline__ u64 fmul2(u64 a, u64 b) {
    u64 d; asm("mul.rn.f32x2 %0,%1,%2;" : "=l"(d) : "l"(a), "l"(b)); return d;
}
__device__ __forceinline__ u64 fadd2(u64 a, u64 b) {
    u64 d; asm("add.rn.f32x2 %0,%1,%2;" : "=l"(d) : "l"(a), "l"(b)); return d;
}
__device__ __forceinline__ float ex2f(float x) {
    float r; asm("ex2.approx.f32 %0,%1;" : "=f"(r) : "f"(x)); return r;
}

struct Params {
    const int   *dt, *ds, *sl;
    const float *emb_dice, *emb_star, *emb_btns;
    const float *Wqkv[2], *bqkv[2], *Wo[2], *bo[2], *Wl[2], *bl[2];
    const float *Wout, *bout;
    float *out;
    int B;
};

struct __align__(16) GW {
    u64 t0[32][14];     // layer-0 qkv table; [0..3]=q (pre-scaled), [4..7]=k, [8..11]=v
    u64 Wq1[12][8];     // layer-1 Wqkv row pairs (r, r+4); q rows pre-scaled
    u64 bq1[12];
    u64 Wo2[2][4][8];   // row pairs (2p, 2p+1)
    u64 bo2[2][4];
    u64 Wl2[2][4][8];
    u64 bl2[2][4];
    u64 Wout2[20][4];
    float bout[20];
    float pad[4];
};
__device__ GW g_w;

// ---------------- prep: pack everything once ----------------
__global__ void prep_kernel(Params p) {
    int i = blockIdx.x * blockDim.x + threadIdx.x;
    const float S = 0.72134752f;   // 0.5 * log2(e): hd^-0.5 and exp->ex2 folded
    if (i < 384) {
        int id = i / 12, pp = i % 12;
        int gg = pp >> 2, r = pp & 3;
        int r0 = gg * 8 + r, r1 = r0 + 4;
        const float *e = (id < 15) ? p.emb_dice + id * 8
                        : (id < 30) ? p.emb_star + (id - 15) * 8
                                    : p.emb_btns + (id - 30) * 8;
        const float *w0 = p.Wqkv[0] + r0 * 8;
        const float *w1 = p.Wqkv[0] + r1 * 8;
        u64 acc = pk2(p.bqkv[0][r0], p.bqkv[0][r1]);
        #pragma unroll
        for (int j = 0; j < 8; j++)
            acc = ffma2(pk2(e[j], e[j]), pk2(w0[j], w1[j]), acc);
        if (pp < 4) acc = fmul2(acc, pk2(S, S));
        g_w.t0[id][pp] = acc;
    } else if (i < 480) {
        int k = i - 384; int pp = k >> 3, j = k & 7;
        int gg = pp >> 2, r = pp & 3, r0 = gg * 8 + r, r1 = r0 + 4;
        u64 w = pk2(p.Wqkv[1][r0 * 8 + j], p.Wqkv[1][r1 * 8 + j]);
        if (pp < 4) w = fmul2(w, pk2(S, S));
        g_w.Wq1[pp][j] = w;
    } else if (i < 492) {
        int pp = i - 480; int gg = pp >> 2, r = pp & 3, r0 = gg * 8 + r;
        u64 w = pk2(p.bqkv[1][r0], p.bqkv[1][r0 + 4]);
        if (pp < 4) w = fmul2(w, pk2(S, S));
        g_w.bq1[pp] = w;
    } else if (i < 556) {
        int k = i - 492; int l = k >> 5, pr = (k >> 3) & 3, j = k & 7;
        g_w.Wo2[l][pr][j] = pk2(p.Wo[l][2 * pr * 8 + j], p.Wo[l][(2 * pr + 1) * 8 + j]);
    } else if (i < 564) {
        int k = i - 556; int l = k >> 2, pr = k & 3;
        g_w.bo2[l][pr] = pk2(p.bo[l][2 * pr], p.bo[l][2 * pr + 1]);
    } else if (i < 628) {
        int k = i - 564; int l = k >> 5, pr = (k >> 3) & 3, j = k & 7;
        g_w.Wl2[l][pr][j] = pk2(p.Wl[l][2 * pr * 8 + j], p.Wl[l][(2 * pr + 1) * 8 + j]);
    } else if (i < 636) {
        int k = i - 628; int l = k >> 2, pr = k & 3;
        g_w.bl2[l][pr] = pk2(p.bl[l][2 * pr], p.bl[l][2 * pr + 1]);
    } else if (i < 716) {
        int k = i - 636; int a = k >> 2, j = k & 3;
        g_w.Wout2[a][j] = pk2(p.Wout[a * 8 + 2 * j], p.Wout[a * 8 + 2 * j + 1]);
    } else if (i < 736) {
        g_w.bout[i - 716] = p.bout[i - 716];
    }
}

// ---------------- attention + o-proj + MLP for 2 tokens ----------------
__device__ __forceinline__ void attn2(
    const u64 *qA2, const u64 *qB2, const u64 *kvg,
    float *xA, float *xB,
    const u64 (*wo2)[8], const u64 *bo2,
    const u64 (*wl2)[8], const u64 *bl2)
{
    __syncwarp();   // kv writes (all group lanes) -> kv reads
    u64 sumA = 0, sumB = 0;
    u64 avA0 = 0, avA1 = 0, avA2 = 0, avA3 = 0;
    u64 avB0 = 0, avB1 = 0, avB2 = 0, avB3 = 0;
    #pragma unroll
    for (int t = 0; t < 15; t++) {
        const u64 *row = kvg + t * 10;
        u64x2 k01 = *(const u64x2 *)(row);
        u64x2 k23 = *(const u64x2 *)(row + 2);
        u64x2 v01 = *(const u64x2 *)(row + 4);
        u64x2 v23 = *(const u64x2 *)(row + 6);
        {
            u64 s2 = fmul2(qA2[0], k01.x);
            s2 = ffma2(qA2[1], k01.y, s2);
            s2 = ffma2(qA2[2], k23.x, s2);
            s2 = ffma2(qA2[3], k23.y, s2);
            float f0, f1; upk2(s2, f0, f1);
            u64 w = pk2(ex2f(f0), ex2f(f1));
            sumA = fadd2(sumA, w);
            avA0 = ffma2(w, v01.x, avA0); avA1 = ffma2(w, v01.y, avA1);
            avA2 = ffma2(w, v23.x, avA2); avA3 = ffma2(w, v23.y, avA3);
        }
        {
            u64 s2 = fmul2(qB2[0], k01.x);
            s2 = ffma2(qB2[1], k01.y, s2);
            s2 = ffma2(qB2[2], k23.x, s2);
            s2 = ffma2(qB2[3], k23.y, s2);
            float f0, f1; upk2(s2, f0, f1);
            u64 w = pk2(ex2f(f0), ex2f(f1));
            sumB = fadd2(sumB, w);
            avB0 = ffma2(w, v01.x, avB0); avB1 = ffma2(w, v01.y, avB1);
            avB2 = ffma2(w, v23.x, avB2); avB3 = ffma2(w, v23.y, avB3);
        }
    }
    float a0, a1, b0, b1;
    upk2(sumA, a0, a1);
    u64 invA = pk2(__fdividef(1.f, a0), __fdividef(1.f, a1));
    upk2(sumB, b0, b1);
    u64 invB = pk2(__fdividef(1.f, b0), __fdividef(1.f, b1));

    float oA[8], oB[8];
    { u64 t = fmul2(avA0, invA); upk2(t, oA[0], oA[4]); }
    { u64 t = fmul2(avA1, invA); upk2(t, oA[1], oA[5]); }
    { u64 t = fmul2(avA2, invA); upk2(t, oA[2], oA[6]); }
    { u64 t = fmul2(avA3, invA); upk2(t, oA[3], oA[7]); }
    { u64 t = fmul2(avB0, invB); upk2(t, oB[0], oB[4]); }
    { u64 t = fmul2(avB1, invB); upk2(t, oB[1], oB[5]); }
    { u64 t = fmul2(avB2, invB); upk2(t, oB[2], oB[6]); }
    { u64 t = fmul2(avB3, invB); upk2(t, oB[3], oB[7]); }

    // o projection + residual
    u64 odA[8], odB[8];
    #pragma unroll
    for (int i = 0; i < 8; i++) { odA[i] = pk2(oA[i], oA[i]); odB[i] = pk2(oB[i], oB[i]); }
    float xoA[8], xoB[8];
    #pragma unroll
    for (int pr = 0; pr < 4; pr++) {
        const u64x2 *wp = (const u64x2 *)wo2[pr];
        u64x2 w01 = wp[0], w23 = wp[1], w45 = wp[2], w67 = wp[3];
        u64 bb = bo2[pr];
        u64 acc = ffma2(odA[0], w01.x, bb);
        acc = ffma2(odA[1], w01.y, acc); acc = ffma2(odA[2], w23.x, acc);
        acc = ffma2(odA[3], w23.y, acc); acc = ffma2(odA[4], w45.x, acc);
        acc = ffma2(odA[5], w45.y, acc); acc = ffma2(odA[6], w67.x, acc);
        acc = ffma2(odA[7], w67.y, acc);
        float r0, r1; upk2(acc, r0, r1);
        xoA[2 * pr] = xA[2 * pr] + r0; xoA[2 * pr + 1] = xA[2 * pr + 1] + r1;
        acc = ffma2(odB[0], w01.x, bb);
        acc = ffma2(odB[1], w01.y, acc); acc = ffma2(odB[2], w23.x, acc);
        acc = ffma2(odB[3], w23.y, acc); acc = ffma2(odB[4], w45.x, acc);
        acc = ffma2(odB[5], w45.y, acc); acc = ffma2(odB[6], w67.x, acc);
        acc = ffma2(odB[7], w67.y, acc);
        upk2(acc, r0, r1);
        xoB[2 * pr] = xB[2 * pr] + r0; xoB[2 * pr + 1] = xB[2 * pr + 1] + r1;
    }
    // linear + relu + residual
    u64 xdA[8], xdB[8];
    #pragma unroll
    for (int i = 0; i < 8; i++) { xdA[i] = pk2(xoA[i], xoA[i]); xdB[i] = pk2(xoB[i], xoB[i]); }
    #pragma unroll
    for (int pr = 0; pr < 4; pr++) {
        const u64x2 *wp = (const u64x2 *)wl2[pr];
        u64x2 w01 = wp[0], w23 = wp[1], w45 = wp[2], w67 = wp[3];
        u64 bb = bl2[pr];
        u64 acc = ffma2(xdA[0], w01.x, bb);
        acc = ffma2(xdA[1], w01.y, acc); acc = ffma2(xdA[2], w23.x, acc);
        acc = ffma2(xdA[3], w23.y, acc); acc = ffma2(xdA[4], w45.x, acc);
        acc = ffma2(xdA[5], w45.y, acc); acc = ffma2(xdA[6], w67.x, acc);
        acc = ffma2(xdA[7], w67.y, acc);
        float r0, r1; upk2(acc, r0, r1);
        xA[2 * pr]     = xoA[2 * pr]     + fmaxf(r0, 0.f);
        xA[2 * pr + 1] = xoA[2 * pr + 1] + fmaxf(r1, 0.f);
        acc = ffma2(xdB[0], w01.x, bb);
        acc = ffma2(xdB[1], w01.y, acc); acc = ffma2(xdB[2], w23.x, acc);
        acc = ffma2(xdB[3], w23.y, acc); acc = ffma2(xdB[4], w45.x, acc);
        acc = ffma2(xdB[5], w45.y, acc); acc = ffma2(xdB[6], w67.x, acc);
        acc = ffma2(xdB[7], w67.y, acc);
        upk2(acc, r0, r1);
        xB[2 * pr]     = xoB[2 * pr]     + fmaxf(r0, 0.f);
        xB[2 * pr + 1] = xoB[2 * pr + 1] + fmaxf(r1, 0.f);
    }
}

__global__ void __launch_bounds__(TPB) bot_kernel(Params p) {
    __shared__ __align__(16) GW sw;                 // 6336 B
    __shared__ __align__(16) float semb[32 * 36];   // padded rows, 4608 B
    // kv: [warp][group][148 u64]; token row stride = 10 u64 (80B), 15 rows used.
    // group stride 148*8=1184B (%128==32 -> conflict-free broadcast reads across groups)
    __shared__ __align__(16) u64 kvs[NW][4][148];   // 37888 B

    const int tid = threadIdx.x;
    // stage packed weights + tables
    {
        const u64x2 *src = (const u64x2 *)&g_w;
        u64x2 *dst = (u64x2 *)&sw;
        for (int i = tid; i < (int)(sizeof(GW) / 16); i += TPB) dst[i] = src[i];
        for (int i = tid; i < 256; i += TPB) {
            float v; int id, j;
            if (i < 120)      { v = p.emb_dice[i];       id = i >> 3;              j = i & 7; }
            else if (i < 240) { v = p.emb_star[i - 120]; id = 15 + ((i - 120) >> 3); j = (i - 120) & 7; }
            else              { v = p.emb_btns[i - 240]; id = 30 + ((i - 240) >> 3); j = (i - 240) & 7; }
            semb[id * 36 + j] = v;
        }
    }
    __syncthreads();

    const int warp = tid >> 5, lane = tid & 31;
    const int g = lane >> 3, s = lane & 7;
    const int b = blockIdx.x * SPB + warp * 4 + g;
    const bool valid = (b < p.B);
    const int tA = 2 * s, tB = 2 * s + 1;   // tB==15 for s==7 -> dummy

    int idA = 0, idB = 30;
    if (valid) {
        const int base = b * 5;
        idA = (tA < 5) ? p.dt[base + tA]
            : (tA < 10) ? 15 + p.ds[base + tA - 5]
                        : 30 + p.sl[base + tA - 10];
        if (tB < 15)
            idB = (tB < 5) ? p.dt[base + tB]
                : (tB < 10) ? 15 + p.ds[base + tB - 5]
                            : 30 + p.sl[base + tB - 10];
    }

    float xA[8], xB[8];
    {
        const float4 *ea = (const float4 *)&semb[idA * 36];
        float4 e0 = ea[0], e1 = ea[1];
        xA[0] = e0.x; xA[1] = e0.y; xA[2] = e0.z; xA[3] = e0.w;
        xA[4] = e1.x; xA[5] = e1.y; xA[6] = e1.z; xA[7] = e1.w;
        const float4 *eb = (const float4 *)&semb[idB * 36];
        float4 f0 = eb[0], f1 = eb[1];
        xB[0] = f0.x; xB[1] = f0.y; xB[2] = f0.z; xB[3] = f0.w;
        xB[4] = f1.x; xB[5] = f1.y; xB[6] = f1.z; xB[7] = f1.w;
    }

    u64 *kvg = &kvs[warp][g][0];
    u64 *rowA = kvg + tA * 10;
    u64 *rowB = kvg + tB * 10;   // only written when s<7
    u64 qA2[4], qB2[4];

    // ---- layer 0: table lookup ----
    {
        const u64 *ta = sw.t0[idA];
        u64x2 a0 = *(const u64x2 *)(ta), a1 = *(const u64x2 *)(ta + 2);
        qA2[0] = a0.x; qA2[1] = a0.y; qA2[2] = a1.x; qA2[3] = a1.y;
        *(u64x2 *)(rowA)     = *(const u64x2 *)(ta + 4);
        *(u64x2 *)(rowA + 2) = *(const u64x2 *)(ta + 6);
        *(u64x2 *)(rowA + 4) = *(const u64x2 *)(ta + 8);
        *(u64x2 *)(rowA + 6) = *(const u64x2 *)(ta + 10);
        const u64 *tb = sw.t0[idB];
        u64x2 b0 = *(const u64x2 *)(tb), b1 = *(const u64x2 *)(tb + 2);
        qB2[0] = b0.x; qB2[1] = b0.y; qB2[2] = b1.x; qB2[3] = b1.y;
        if (s < 7) {
            *(u64x2 *)(rowB)     = *(const u64x2 *)(tb + 4);
            *(u64x2 *)(rowB + 2) = *(const u64x2 *)(tb + 6);
            *(u64x2 *)(rowB + 4) = *(const u64x2 *)(tb + 8);
            *(u64x2 *)(rowB + 6) = *(const u64x2 *)(tb + 10);
        }
    }
    attn2(qA2, qB2, kvg, xA, xB, sw.Wo2[0], sw.bo2[0], sw.Wl2[0], sw.bl2[0]);

    // ---- layer 1: qkv via packed row pairs (weights shared across both tokens) ----
    __syncwarp();   // layer-0 kv reads complete before overwrite
    {
        u64 xdA[8], xdB[8];
        #pragma unroll
        for (int i = 0; i < 8; i++) { xdA[i] = pk2(xA[i], xA[i]); xdB[i] = pk2(xB[i], xB[i]); }
        u64 holdA = 0, holdB = 0;
        #pragma unroll
        for (int pr = 0; pr < 12; pr++) {
            const u64x2 *wp = (const u64x2 *)sw.Wq1[pr];
            u64x2 w01 = wp[0], w23 = wp[1], w45 = wp[2], w67 = wp[3];
            u64 bb = sw.bq1[pr];
            u64 a = ffma2(xdA[0], w01.x, bb);
            a = ffma2(xdA[1], w01.y, a); a = ffma2(xdA[2], w23.x, a);
            a = ffma2(xdA[3], w23.y, a); a = ffma2(xdA[4], w45.x, a);
            a = ffma2(xdA[5], w45.y, a); a = ffma2(xdA[6], w67.x, a);
            a = ffma2(xdA[7], w67.y, a);
            u64 c = ffma2(xdB[0], w01.x, bb);
            c = ffma2(xdB[1], w01.y, c); c = ffma2(xdB[2], w23.x, c);
            c = ffma2(xdB[3], w23.y, c); c = ffma2(xdB[4], w45.x, c);
            c = ffma2(xdB[5], w45.y, c); c = ffma2(xdB[6], w67.x, c);
            c = ffma2(xdB[7], w67.y, c);
            if (pr < 4) { qA2[pr] = a; qB2[pr] = c; }
            else if ((pr & 1) == 0) { holdA = a; holdB = c; }
            else {
                const int off = pr - 5;            // 0,2,4,6 -> k0k1,k2k3,v0v1,v2v3
                u64x2 st; st.x = holdA; st.y = a;
                *(u64x2 *)(rowA + off) = st;
                if (s < 7) { st.x = holdB; st.y = c; *(u64x2 *)(rowB + off) = st; }
            }
        }
    }
    attn2(qA2, qB2, kvg, xA, xB, sw.Wo2[1], sw.bo2[1], sw.Wl2[1], sw.bl2[1]);

    // ---- mean pool over 15 tokens (8-lane groups) ----
    float xp[8];
    #pragma unroll
    for (int j = 0; j < 8; j++) {
        float v = xA[j] + ((s < 7) ? xB[j] : 0.f);
        v += __shfl_xor_sync(0xffffffffu, v, 1);
        v += __shfl_xor_sync(0xffffffffu, v, 2);
        v += __shfl_xor_sync(0xffffffffu, v, 4);
        xp[j] = v * (1.0f / 15.0f);
    }

    // ---- output projection: a = s, s+8, and (s<4) s+16 ----
    if (valid) {
        u64 xq[4];
        #pragma unroll
        for (int i = 0; i < 4; i++) xq[i] = pk2(xp[2 * i], xp[2 * i + 1]);
        #pragma unroll
        for (int rep = 0; rep < 3; rep++) {
            const int a = s + 8 * rep;
            if (rep == 2 && s >= 4) break;
            const u64x2 *wp = (const u64x2 *)sw.Wout2[a];
            u64x2 w01 = wp[0], w23 = wp[1];
            u64 acc = fmul2(xq[0], w01.x);
            acc = ffma2(xq[1], w01.y, acc);
            acc = ffma2(xq[2], w23.x, acc);
            acc = ffma2(xq[3], w23.y, acc);
            float r0, r1; upk2(acc, r0, r1);
            p.out[b * 20 + a] = sw.bout[a] + r0 + r1;
        }
    }
}

extern "C" void kernel_launch(void* const* d_in, const int* in_sizes, int n_in,
                              void* d_out, int out_size) {
    Params p;
    p.dt = (const int *)d_in[0];
    p.ds = (const int *)d_in[1];
    p.sl = (const int *)d_in[2];
    p.emb_dice = (const float *)d_in[3];
    p.emb_star = (const float *)d_in[4];
    p.emb_btns = (const float *)d_in[5];

    int layer_base, wout_i, bout_i;
    if (in_sizes[6] == 160) { wout_i = 6; bout_i = 7; layer_base = 8; }
    else                    { layer_base = 6; wout_i = 18; bout_i = 19; }

    for (int l = 0; l < 2; l++) {
        int o = layer_base + 6 * l;
        p.Wqkv[l] = (const float *)d_in[o];
        p.bqkv[l] = (const float *)d_in[o + 1];
        p.Wo[l]   = (const float *)d_in[o + 2];
        p.bo[l]   = (const float *)d_in[o + 3];
        p.Wl[l]   = (const float *)d_in[o + 4];
        p.bl[l]   = (const float *)d_in[o + 5];
    }
    p.Wout = (const float *)d_in[wout_i];
    p.bout = (const float *)d_in[bout_i];
    p.out  = (float *)d_out;
    p.B    = in_sizes[0] / 5;

    prep_kernel<<<3, 256>>>(p);
    int blocks = (p.B + SPB - 1) / SPB;
    bot_kernel<<<blocks, TPB>>>(p);
}

// round 4
// speedup vs baseline: 1.3823x; 1.3823x over previous
#include <cuda_runtime.h>

// BetterBot round-4: back to 1 token/lane (2 samples/warp), fused one-pass
// softmax (no score array), conflict-free kv half-buffers (+64B mod 128),
// prep-kernel-packed weights, ex2.approx with 0.5*log2e folded into q.

#define TPB 256
#define NW  8
#define SPB 16   // samples per block

typedef unsigned long long u64;
typedef ulonglong2 u64x2;

__device__ __forceinline__ u64 pk2(float lo, float hi) {
    u64 r; asm("mov.b64 %0,{%1,%2};" : "=l"(r) : "f"(lo), "f"(hi)); return r;
}
__device__ __forceinline__ void upk2(u64 v, float &lo, float &hi) {
    asm("mov.b64 {%0,%1},%2;" : "=f"(lo), "=f"(hi) : "l"(v));
}
__device__ __forceinline__ u64 ffma2(u64 a, u64 b, u64 c) {
    u64 d; asm("fma.rn.f32x2 %0,%1,%2,%3;" : "=l"(d) : "l"(a), "l"(b), "l"(c)); return d;
}
__device__ __forceinline__ u64 fmul2(u64 a, u64 b) {
    u64 d; asm("mul.rn.f32x2 %0,%1,%2;" : "=l"(d) : "l"(a), "l"(b)); return d;
}
__device__ __forceinline__ u64 fadd2(u64 a, u64 b) {
    u64 d; asm("add.rn.f32x2 %0,%1,%2;" : "=l"(d) : "l"(a), "l"(b)); return d;
}
__device__ __forceinline__ float ex2f(float x) {
    float r; asm("ex2.approx.f32 %0,%1;" : "=f"(r) : "f"(x)); return r;
}

struct Params {
    const int   *dt, *ds, *sl;
    const float *emb_dice, *emb_star, *emb_btns;
    const float *Wqkv[2], *bqkv[2], *Wo[2], *bo[2], *Wl[2], *bl[2];
    const float *Wout, *bout;
    float *out;
    int B;
};

struct __align__(16) GW {
    u64 t0[32][12];     // layer-0 qkv: [0..3]=q2 (pre-scaled), [4..7]=k2, [8..11]=v2
    u64 Wq1[12][8];     // layer-1 Wqkv row pairs (g*8+r, g*8+r+4); q rows pre-scaled
    u64 bq1[12];
    u64 Wo2[2][4][8];   // row pairs (2p, 2p+1)
    u64 bo2[2][4];
    u64 Wl2[2][4][8];
    u64 bl2[2][4];
    u64 Wout2[20][4];
    float bout[20];
    float emb[32][8];
    float pad[4];
};
__device__ GW g_w;

__global__ void prep_kernel(Params p) {
    int i = blockIdx.x * blockDim.x + threadIdx.x;
    const float S = 0.72134752f;   // 0.5 * log2(e)
    if (i < 384) {
        int id = i / 12, pp = i % 12;
        int gg = pp >> 2, r = pp & 3;
        int r0 = gg * 8 + r, r1 = r0 + 4;
        const float *e = (id < 15) ? p.emb_dice + id * 8
                        : (id < 30) ? p.emb_star + (id - 15) * 8
                                    : p.emb_btns + (id - 30) * 8;
        const float *w0 = p.Wqkv[0] + r0 * 8;
        const float *w1 = p.Wqkv[0] + r1 * 8;
        u64 acc = pk2(p.bqkv[0][r0], p.bqkv[0][r1]);
        #pragma unroll
        for (int j = 0; j < 8; j++)
            acc = ffma2(pk2(e[j], e[j]), pk2(w0[j], w1[j]), acc);
        if (pp < 4) acc = fmul2(acc, pk2(S, S));
        g_w.t0[id][pp] = acc;
    } else if (i < 480) {
        int k = i - 384; int pp = k >> 3, j = k & 7;
        int gg = pp >> 2, r = pp & 3, r0 = gg * 8 + r, r1 = r0 + 4;
        u64 w = pk2(p.Wqkv[1][r0 * 8 + j], p.Wqkv[1][r1 * 8 + j]);
        if (pp < 4) w = fmul2(w, pk2(S, S));
        g_w.Wq1[pp][j] = w;
    } else if (i < 492) {
        int pp = i - 480; int gg = pp >> 2, r = pp & 3, r0 = gg * 8 + r;
        u64 w = pk2(p.bqkv[1][r0], p.bqkv[1][r0 + 4]);
        if (pp < 4) w = fmul2(w, pk2(S, S));
        g_w.bq1[pp] = w;
    } else if (i < 556) {
        int k = i - 492; int l = k >> 5, pr = (k >> 3) & 3, j = k & 7;
        g_w.Wo2[l][pr][j] = pk2(p.Wo[l][2 * pr * 8 + j], p.Wo[l][(2 * pr + 1) * 8 + j]);
    } else if (i < 564) {
        int k = i - 556; int l = k >> 2, pr = k & 3;
        g_w.bo2[l][pr] = pk2(p.bo[l][2 * pr], p.bo[l][2 * pr + 1]);
    } else if (i < 628) {
        int k = i - 564; int l = k >> 5, pr = (k >> 3) & 3, j = k & 7;
        g_w.Wl2[l][pr][j] = pk2(p.Wl[l][2 * pr * 8 + j], p.Wl[l][(2 * pr + 1) * 8 + j]);
    } else if (i < 636) {
        int k = i - 628; int l = k >> 2, pr = k & 3;
        g_w.bl2[l][pr] = pk2(p.bl[l][2 * pr], p.bl[l][2 * pr + 1]);
    } else if (i < 716) {
        int k = i - 636; int a = k >> 2, j = k & 3;
        g_w.Wout2[a][j] = pk2(p.Wout[a * 8 + 2 * j], p.Wout[a * 8 + 2 * j + 1]);
    } else if (i < 736) {
        g_w.bout[i - 716] = p.bout[i - 716];
    } else if (i < 992) {
        int k = i - 736; int id = k >> 3, j = k & 7;
        const float *e = (id < 15) ? p.emb_dice + id * 8
                        : (id < 30) ? p.emb_star + (id - 15) * 8
                                    : p.emb_btns + (id - 30) * 8;
        g_w.emb[id][j] = e[j];
    }
}

// fused attention + o-proj + MLP for one token
__device__ __forceinline__ void attn1(
    const u64 *q2, const u64 *kvh, float *x,
    const u64 (*wo2)[8], const u64 *bo2,
    const u64 (*wl2)[8], const u64 *bl2)
{
    __syncwarp();   // kv writes -> kv reads
    u64 sum2 = 0, av0 = 0, av1 = 0, av2 = 0, av3 = 0;
    #pragma unroll
    for (int t = 0; t < 15; t++) {
        const u64 *row = kvh + t * 10;
        u64x2 k01 = *(const u64x2 *)(row);
        u64x2 k23 = *(const u64x2 *)(row + 2);
        u64 s2 = fmul2(q2[0], k01.x);
        s2 = ffma2(q2[1], k01.y, s2);
        s2 = ffma2(q2[2], k23.x, s2);
        s2 = ffma2(q2[3], k23.y, s2);
        float f0, f1; upk2(s2, f0, f1);
        u64 w = pk2(ex2f(f0), ex2f(f1));
        u64x2 v01 = *(const u64x2 *)(row + 4);
        u64x2 v23 = *(const u64x2 *)(row + 6);
        sum2 = fadd2(sum2, w);
        av0 = ffma2(w, v01.x, av0); av1 = ffma2(w, v01.y, av1);
        av2 = ffma2(w, v23.x, av2); av3 = ffma2(w, v23.y, av3);
    }
    float s0, s1; upk2(sum2, s0, s1);
    u64 inv = pk2(__fdividef(1.f, s0), __fdividef(1.f, s1));
    float o[8];
    { u64 t = fmul2(av0, inv); upk2(t, o[0], o[4]); }
    { u64 t = fmul2(av1, inv); upk2(t, o[1], o[5]); }
    { u64 t = fmul2(av2, inv); upk2(t, o[2], o[6]); }
    { u64 t = fmul2(av3, inv); upk2(t, o[3], o[7]); }

    u64 od[8];
    #pragma unroll
    for (int i = 0; i < 8; i++) od[i] = pk2(o[i], o[i]);
    float xo[8];
    #pragma unroll
    for (int pr = 0; pr < 4; pr++) {
        const u64x2 *wp = (const u64x2 *)wo2[pr];
        u64x2 w01 = wp[0], w23 = wp[1], w45 = wp[2], w67 = wp[3];
        u64 acc = ffma2(od[0], w01.x, bo2[pr]);
        acc = ffma2(od[1], w01.y, acc); acc = ffma2(od[2], w23.x, acc);
        acc = ffma2(od[3], w23.y, acc); acc = ffma2(od[4], w45.x, acc);
        acc = ffma2(od[5], w45.y, acc); acc = ffma2(od[6], w67.x, acc);
        acc = ffma2(od[7], w67.y, acc);
        float r0, r1; upk2(acc, r0, r1);
        xo[2 * pr] = x[2 * pr] + r0; xo[2 * pr + 1] = x[2 * pr + 1] + r1;
    }
    u64 xd[8];
    #pragma unroll
    for (int i = 0; i < 8; i++) xd[i] = pk2(xo[i], xo[i]);
    #pragma unroll
    for (int pr = 0; pr < 4; pr++) {
        const u64x2 *wp = (const u64x2 *)wl2[pr];
        u64x2 w01 = wp[0], w23 = wp[1], w45 = wp[2], w67 = wp[3];
        u64 acc = ffma2(xd[0], w01.x, bl2[pr]);
        acc = ffma2(xd[1], w01.y, acc); acc = ffma2(xd[2], w23.x, acc);
        acc = ffma2(xd[3], w23.y, acc); acc = ffma2(xd[4], w45.x, acc);
        acc = ffma2(xd[5], w45.y, acc); acc = ffma2(xd[6], w67.x, acc);
        acc = ffma2(xd[7], w67.y, acc);
        float r0, r1; upk2(acc, r0, r1);
        x[2 * pr]     = xo[2 * pr]     + fmaxf(r0, 0.f);
        x[2 * pr + 1] = xo[2 * pr + 1] + fmaxf(r1, 0.f);
    }
}

__global__ void __launch_bounds__(TPB, 4) bot_kernel(Params p) {
    __shared__ __align__(16) GW sw;                  // 6848 B
    // kv: [warp][half][168 u64]; half stride 1344 B (%128 == 64 -> the two
    // halves' broadcast reads land in different bank quads; conflict-free).
    // token row = 10 u64: k01,k23,v01,v23,pad2.
    __shared__ __align__(16) u64 kvs[NW][2][168];    // 21504 B

    const int tid = threadIdx.x;
    {
        const u64x2 *src = (const u64x2 *)&g_w;
        u64x2 *dst = (u64x2 *)&sw;
        #pragma unroll
        for (int k = 0; k < 2; k++) {
            int i = tid + k * TPB;
            if (i < (int)(sizeof(GW) / 16)) dst[i] = src[i];
        }
    }
    __syncthreads();

    const int warp = tid >> 5, lane = tid & 31;
    const int half = lane >> 4, s = lane & 15;
    const int b = blockIdx.x * SPB + warp * 2 + half;
    const bool tok = (s < 15);

    int id = 30;   // lane 15 dummy
    if (tok) {
        const int base = b * 5;
        id = (s < 5) ? p.dt[base + s]
           : (s < 10) ? 15 + p.ds[base + s - 5]
                      : 30 + p.sl[base + s - 10];
    }

    float x[8];
    {
        const float4 *e = (const float4 *)&sw.emb[id][0];
        float4 e0 = e[0], e1 = e[1];
        x[0] = e0.x; x[1] = e0.y; x[2] = e0.z; x[3] = e0.w;
        x[4] = e1.x; x[5] = e1.y; x[6] = e1.z; x[7] = e1.w;
    }

    u64 *kvh = &kvs[warp][half][0];
    u64 *row = kvh + s * 10;
    u64 q2[4];

    // ---- layer 0: table lookup ----
    {
        const u64 *ta = sw.t0[id];
        u64x2 a0 = *(const u64x2 *)(ta), a1 = *(const u64x2 *)(ta + 2);
        q2[0] = a0.x; q2[1] = a0.y; q2[2] = a1.x; q2[3] = a1.y;
        if (tok) {
            *(u64x2 *)(row)     = *(const u64x2 *)(ta + 4);
            *(u64x2 *)(row + 2) = *(const u64x2 *)(ta + 6);
            *(u64x2 *)(row + 4) = *(const u64x2 *)(ta + 8);
            *(u64x2 *)(row + 6) = *(const u64x2 *)(ta + 10);
        }
    }
    attn1(q2, kvh, x, sw.Wo2[0], sw.bo2[0], sw.Wl2[0], sw.bl2[0]);

    // ---- layer 1: qkv via packed row pairs ----
    __syncwarp();   // layer-0 kv reads done before overwrite
    {
        u64 xd[8];
        #pragma unroll
        for (int i = 0; i < 8; i++) xd[i] = pk2(x[i], x[i]);
        u64 hold = 0;
        #pragma unroll
        for (int pr = 0; pr < 12; pr++) {
            const u64x2 *wp = (const u64x2 *)sw.Wq1[pr];
            u64x2 w01 = wp[0], w23 = wp[1], w45 = wp[2], w67 = wp[3];
            u64 a = ffma2(xd[0], w01.x, sw.bq1[pr]);
            a = ffma2(xd[1], w01.y, a); a = ffma2(xd[2], w23.x, a);
            a = ffma2(xd[3], w23.y, a); a = ffma2(xd[4], w45.x, a);
            a = ffma2(xd[5], w45.y, a); a = ffma2(xd[6], w67.x, a);
            a = ffma2(xd[7], w67.y, a);
            if (pr < 4) q2[pr] = a;
            else if ((pr & 1) == 0) hold = a;
            else if (tok) {
                u64x2 st; st.x = hold; st.y = a;
                *(u64x2 *)(row + (pr - 5)) = st;   // offsets 0,2,4,6
            }
        }
    }
    attn1(q2, kvh, x, sw.Wo2[1], sw.bo2[1], sw.Wl2[1], sw.bl2[1]);

    // ---- mean pool over 15 tokens (16-lane groups) ----
    #pragma unroll
    for (int j = 0; j < 8; j++) {
        float v = tok ? x[j] : 0.f;
        v += __shfl_xor_sync(0xffffffffu, v, 1);
        v += __shfl_xor_sync(0xffffffffu, v, 2);
        v += __shfl_xor_sync(0xffffffffu, v, 4);
        v += __shfl_xor_sync(0xffffffffu, v, 8);
        x[j] = v * (1.0f / 15.0f);
    }

    // ---- output projection ----
    if (b < p.B) {
        u64 xq[4];
        #pragma unroll
        for (int i = 0; i < 4; i++) xq[i] = pk2(x[2 * i], x[2 * i + 1]);
        {
            const u64x2 *wp = (const u64x2 *)sw.Wout2[s];
            u64x2 w01 = wp[0], w23 = wp[1];
            u64 acc = fmul2(xq[0], w01.x);
            acc = ffma2(xq[1], w01.y, acc);
            acc = ffma2(xq[2], w23.x, acc);
            acc = ffma2(xq[3], w23.y, acc);
            float r0, r1; upk2(acc, r0, r1);
            p.out[b * 20 + s] = sw.bout[s] + r0 + r1;
        }
        if (s < 4) {
            const int a = s + 16;
            const u64x2 *wp = (const u64x2 *)sw.Wout2[a];
            u64x2 w01 = wp[0], w23 = wp[1];
            u64 acc = fmul2(xq[0], w01.x);
            acc = ffma2(xq[1], w01.y, acc);
            acc = ffma2(xq[2], w23.x, acc);
            acc = ffma2(xq[3], w23.y, acc);
            float r0, r1; upk2(acc, r0, r1);
            p.out[b * 20 + a] = sw.bout[a] + r0 + r1;
        }
    }
}

extern "C" void kernel_launch(void* const* d_in, const int* in_sizes, int n_in,
                              void* d_out, int out_size) {
    Params p;
    p.dt = (const int *)d_in[0];
    p.ds = (const int *)d_in[1];
    p.sl = (const int *)d_in[2];
    p.emb_dice = (const float *)d_in[3];
    p.emb_star = (const float *)d_in[4];
    p.emb_btns = (const float *)d_in[5];

    int layer_base, wout_i, bout_i;
    if (in_sizes[6] == 160) { wout_i = 6; bout_i = 7; layer_base = 8; }
    else                    { layer_base = 6; wout_i = 18; bout_i = 19; }

    for (int l = 0; l < 2; l++) {
        int o = layer_base + 6 * l;
        p.Wqkv[l] = (const float *)d_in[o];
        p.bqkv[l] = (const float *)d_in[o + 1];
        p.Wo[l]   = (const float *)d_in[o + 2];
        p.bo[l]   = (const float *)d_in[o + 3];
        p.Wl[l]   = (const float *)d_in[o + 4];
        p.bl[l]   = (const float *)d_in[o + 5];
    }
    p.Wout = (const float *)d_in[wout_i];
    p.bout = (const float *)d_in[bout_i];
    p.out  = (float *)d_out;
    p.B    = in_sizes[0] / 5;

    prep_kernel<<<4, 256>>>(p);
    int blocks = (p.B + SPB - 1) / SPB;
    bot_kernel<<<blocks, TPB>>>(p);
}

// round 5
// speedup vs baseline: 1.3867x; 1.0032x over previous
#include <cuda_runtime.h>

// BetterBot round-5: 2 tokens/lane (8 lanes/sample, 4 samples/warp), dual fused
// one-pass softmax, all weight/kv LDS amortized over 2 tokens, x held in
// out-pair f32x2 form, __launch_bounds__(256,3) for 24-warp residency.

#define TPB 256
#define NW  8
#define SPB 32   // samples per block

typedef unsigned long long u64;
typedef ulonglong2 u64x2;

__device__ __forceinline__ u64 pk2(float lo, float hi) {
    u64 r; asm("mov.b64 %0,{%1,%2};" : "=l"(r) : "f"(lo), "f"(hi)); return r;
}
__device__ __forceinline__ void upk2(u64 v, float &lo, float &hi) {
    asm("mov.b64 {%0,%1},%2;" : "=f"(lo), "=f"(hi) : "l"(v));
}
__device__ __forceinline__ u64 ffma2(u64 a, u64 b, u64 c) {
    u64 d; asm("fma.rn.f32x2 %0,%1,%2,%3;" : "=l"(d) : "l"(a), "l"(b), "l"(c)); return d;
}
__device__ __forceinline__ u64 fmul2(u64 a, u64 b) {
    u64 d; asm("mul.rn.f32x2 %0,%1,%2;" : "=l"(d) : "l"(a), "l"(b)); return d;
}
__device__ __forceinline__ u64 fadd2(u64 a, u64 b) {
    u64 d; asm("add.rn.f32x2 %0,%1,%2;" : "=l"(d) : "l"(a), "l"(b)); return d;
}
__device__ __forceinline__ float ex2f(float x) {
    float r; asm("ex2.approx.f32 %0,%1;" : "=f"(r) : "f"(x)); return r;
}

struct Params {
    const int   *dt, *ds, *sl;
    const float *emb_dice, *emb_star, *emb_btns;
    const float *Wqkv[2], *bqkv[2], *Wo[2], *bo[2], *Wl[2], *bl[2];
    const float *Wout, *bout;
    float *out;
    int B;
};

struct __align__(16) GW {
    u64 t0[32][14];      // layer-0 qkv: [0..3]=q2 (pre-scaled), [4..7]=k2, [8..11]=v2; 2 pad
    u64 Wq1[12][8];      // layer-1 Wqkv row pairs (g*8+r, g*8+r+4); q rows pre-scaled
    u64 bq1[12];
    u64 Wo2[2][4][8];    // row pairs (2p, 2p+1)
    u64 bo2[2][4];
    u64 Wl2[2][4][8];
    u64 bl2[2][4];
    u64 Wout2[20][4];
    float bout[20];
    float emb[32][12];   // 12-float row stride to spread gather banks
    float pad[12];
};
__device__ GW g_w;

__global__ void prep_kernel(Params p) {
    int i = blockIdx.x * blockDim.x + threadIdx.x;
    const float S = 0.72134752f;   // 0.5 * log2(e)
    if (i < 384) {
        int id = i / 12, pp = i % 12;
        int gg = pp >> 2, r = pp & 3;
        int r0 = gg * 8 + r, r1 = r0 + 4;
        const float *e = (id < 15) ? p.emb_dice + id * 8
                        : (id < 30) ? p.emb_star + (id - 15) * 8
                                    : p.emb_btns + (id - 30) * 8;
        const float *w0 = p.Wqkv[0] + r0 * 8;
        const float *w1 = p.Wqkv[0] + r1 * 8;
        u64 acc = pk2(p.bqkv[0][r0], p.bqkv[0][r1]);
        #pragma unroll
        for (int j = 0; j < 8; j++)
            acc = ffma2(pk2(e[j], e[j]), pk2(w0[j], w1[j]), acc);
        if (pp < 4) acc = fmul2(acc, pk2(S, S));
        g_w.t0[id][pp] = acc;
    } else if (i < 480) {
        int k = i - 384; int pp = k >> 3, j = k & 7;
        int gg = pp >> 2, r = pp & 3, r0 = gg * 8 + r, r1 = r0 + 4;
        u64 w = pk2(p.Wqkv[1][r0 * 8 + j], p.Wqkv[1][r1 * 8 + j]);
        if (pp < 4) w = fmul2(w, pk2(S, S));
        g_w.Wq1[pp][j] = w;
    } else if (i < 492) {
        int pp = i - 480; int gg = pp >> 2, r = pp & 3, r0 = gg * 8 + r;
        u64 w = pk2(p.bqkv[1][r0], p.bqkv[1][r0 + 4]);
        if (pp < 4) w = fmul2(w, pk2(S, S));
        g_w.bq1[pp] = w;
    } else if (i < 556) {
        int k = i - 492; int l = k >> 5, pr = (k >> 3) & 3, j = k & 7;
        g_w.Wo2[l][pr][j] = pk2(p.Wo[l][2 * pr * 8 + j], p.Wo[l][(2 * pr + 1) * 8 + j]);
    } else if (i < 564) {
        int k = i - 556; int l = k >> 2, pr = k & 3;
        g_w.bo2[l][pr] = pk2(p.bo[l][2 * pr], p.bo[l][2 * pr + 1]);
    } else if (i < 628) {
        int k = i - 564; int l = k >> 5, pr = (k >> 3) & 3, j = k & 7;
        g_w.Wl2[l][pr][j] = pk2(p.Wl[l][2 * pr * 8 + j], p.Wl[l][(2 * pr + 1) * 8 + j]);
    } else if (i < 636) {
        int k = i - 628; int l = k >> 2, pr = k & 3;
        g_w.bl2[l][pr] = pk2(p.bl[l][2 * pr], p.bl[l][2 * pr + 1]);
    } else if (i < 716) {
        int k = i - 636; int a = k >> 2, j = k & 3;
        g_w.Wout2[a][j] = pk2(p.Wout[a * 8 + 2 * j], p.Wout[a * 8 + 2 * j + 1]);
    } else if (i < 736) {
        g_w.bout[i - 716] = p.bout[i - 716];
    } else if (i < 992) {
        int k = i - 736; int id = k >> 3, j = k & 7;
        const float *e = (id < 15) ? p.emb_dice + id * 8
                        : (id < 30) ? p.emb_star + (id - 15) * 8
                                    : p.emb_btns + (id - 30) * 8;
        g_w.emb[id][j] = e[j];
    }
}

// dual fused softmax-attention: consumes q pairs, produces normalized av
// (av[i] = {o_i, o_{i+4}}) for both tokens.
__device__ __forceinline__ void attn_dual(
    const u64 *qA2, const u64 *qB2, const u64 *kvg, u64 *avA, u64 *avB)
{
    __syncwarp();   // kv writes (all group lanes) -> kv reads
    u64 sumA = 0, sumB = 0;
    #pragma unroll
    for (int i = 0; i < 4; i++) { avA[i] = 0; avB[i] = 0; }
    #pragma unroll
    for (int t = 0; t < 15; t++) {
        const u64 *row = kvg + t * 8;
        u64x2 k01 = *(const u64x2 *)(row);
        u64x2 k23 = *(const u64x2 *)(row + 2);
        u64x2 v01 = *(const u64x2 *)(row + 4);
        u64x2 v23 = *(const u64x2 *)(row + 6);
        {
            u64 s2 = fmul2(qA2[0], k01.x);
            s2 = ffma2(qA2[1], k01.y, s2);
            s2 = ffma2(qA2[2], k23.x, s2);
            s2 = ffma2(qA2[3], k23.y, s2);
            float f0, f1; upk2(s2, f0, f1);
            u64 w = pk2(ex2f(f0), ex2f(f1));
            sumA = fadd2(sumA, w);
            avA[0] = ffma2(w, v01.x, avA[0]); avA[1] = ffma2(w, v01.y, avA[1]);
            avA[2] = ffma2(w, v23.x, avA[2]); avA[3] = ffma2(w, v23.y, avA[3]);
        }
        {
            u64 s2 = fmul2(qB2[0], k01.x);
            s2 = ffma2(qB2[1], k01.y, s2);
            s2 = ffma2(qB2[2], k23.x, s2);
            s2 = ffma2(qB2[3], k23.y, s2);
            float f0, f1; upk2(s2, f0, f1);
            u64 w = pk2(ex2f(f0), ex2f(f1));
            sumB = fadd2(sumB, w);
            avB[0] = ffma2(w, v01.x, avB[0]); avB[1] = ffma2(w, v01.y, avB[1]);
            avB[2] = ffma2(w, v23.x, avB[2]); avB[3] = ffma2(w, v23.y, avB[3]);
        }
    }
    float a0, a1, b0, b1;
    upk2(sumA, a0, a1);
    u64 invA = pk2(__fdividef(1.f, a0), __fdividef(1.f, a1));
    upk2(sumB, b0, b1);
    u64 invB = pk2(__fdividef(1.f, b0), __fdividef(1.f, b1));
    #pragma unroll
    for (int i = 0; i < 4; i++) { avA[i] = fmul2(avA[i], invA); avB[i] = fmul2(avB[i], invB); }
}

// o-proj + residual + MLP + residual for both tokens; x in out-pair form
// (x[pr] = {x_2pr, x_2pr+1}), updated in place.
__device__ __forceinline__ void ff_dual(
    const u64 *avA, const u64 *avB, u64 *xA, u64 *xB,
    const u64 (*wo2)[8], const u64 *bo2,
    const u64 (*wl2)[8], const u64 *bl2)
{
    u64 odA[8], odB[8];
    #pragma unroll
    for (int i = 0; i < 4; i++) {
        float lo, hi;
        upk2(avA[i], lo, hi); odA[i] = pk2(lo, lo); odA[i + 4] = pk2(hi, hi);
        upk2(avB[i], lo, hi); odB[i] = pk2(lo, lo); odB[i + 4] = pk2(hi, hi);
    }
    u64 xoA[4], xoB[4];
    #pragma unroll
    for (int pr = 0; pr < 4; pr++) {
        const u64x2 *wp = (const u64x2 *)wo2[pr];
        u64x2 w01 = wp[0], w23 = wp[1], w45 = wp[2], w67 = wp[3];
        u64 bb = bo2[pr];
        u64 a = ffma2(odA[0], w01.x, bb);
        a = ffma2(odA[1], w01.y, a); a = ffma2(odA[2], w23.x, a);
        a = ffma2(odA[3], w23.y, a); a = ffma2(odA[4], w45.x, a);
        a = ffma2(odA[5], w45.y, a); a = ffma2(odA[6], w67.x, a);
        a = ffma2(odA[7], w67.y, a);
        xoA[pr] = fadd2(xA[pr], a);
        u64 c = ffma2(odB[0], w01.x, bb);
        c = ffma2(odB[1], w01.y, c); c = ffma2(odB[2], w23.x, c);
        c = ffma2(odB[3], w23.y, c); c = ffma2(odB[4], w45.x, c);
        c = ffma2(odB[5], w45.y, c); c = ffma2(odB[6], w67.x, c);
        c = ffma2(odB[7], w67.y, c);
        xoB[pr] = fadd2(xB[pr], c);
    }
    u64 xdA[8], xdB[8];
    #pragma unroll
    for (int pr = 0; pr < 4; pr++) {
        float lo, hi;
        upk2(xoA[pr], lo, hi); xdA[2 * pr] = pk2(lo, lo); xdA[2 * pr + 1] = pk2(hi, hi);
        upk2(xoB[pr], lo, hi); xdB[2 * pr] = pk2(lo, lo); xdB[2 * pr + 1] = pk2(hi, hi);
    }
    #pragma unroll
    for (int pr = 0; pr < 4; pr++) {
        const u64x2 *wp = (const u64x2 *)wl2[pr];
        u64x2 w01 = wp[0], w23 = wp[1], w45 = wp[2], w67 = wp[3];
        u64 bb = bl2[pr];
        u64 a = ffma2(xdA[0], w01.x, bb);
        a = ffma2(xdA[1], w01.y, a); a = ffma2(xdA[2], w23.x, a);
        a = ffma2(xdA[3], w23.y, a); a = ffma2(xdA[4], w45.x, a);
        a = ffma2(xdA[5], w45.y, a); a = ffma2(xdA[6], w67.x, a);
        a = ffma2(xdA[7], w67.y, a);
        float r0, r1; upk2(a, r0, r1);
        xA[pr] = fadd2(xoA[pr], pk2(fmaxf(r0, 0.f), fmaxf(r1, 0.f)));
        u64 c = ffma2(xdB[0], w01.x, bb);
        c = ffma2(xdB[1], w01.y, c); c = ffma2(xdB[2], w23.x, c);
        c = ffma2(xdB[3], w23.y, c); c = ffma2(xdB[4], w45.x, c);
        c = ffma2(xdB[5], w45.y, c); c = ffma2(xdB[6], w67.x, c);
        c = ffma2(xdB[7], w67.y, c);
        upk2(c, r0, r1);
        xB[pr] = fadd2(xoB[pr], pk2(fmaxf(r0, 0.f), fmaxf(r1, 0.f)));
    }
}

__global__ void __launch_bounds__(TPB, 3) bot_kernel(Params p) {
    __shared__ __align__(16) GW sw;               // 7904 B
    // kv: [warp][group][124 u64]; token row = 8 u64 (k01,k23,v01,v23), 15 rows.
    // group stride 992 B (% 128 == 96) -> the 4 groups' broadcast reads hit
    // disjoint bank quads (offsets 0,24,16,8) -> 1 wavefront per LDS.128.
    __shared__ __align__(16) u64 kvs[NW][4][124]; // 31744 B

    const int tid = threadIdx.x;
    {
        const u64x2 *src = (const u64x2 *)&g_w;
        u64x2 *dst = (u64x2 *)&sw;
        #pragma unroll
        for (int k = 0; k < 2; k++) {
            int i = tid + k * TPB;
            if (i < (int)(sizeof(GW) / 16)) dst[i] = src[i];
        }
    }
    __syncthreads();

    const int warp = tid >> 5, lane = tid & 31;
    const int g = lane >> 3, s = lane & 7;
    const int b = blockIdx.x * SPB + warp * 4 + g;
    const bool valid = (b < p.B);
    const int tA = 2 * s, tB = 2 * s + 1;   // tB==15 for s==7 -> dummy

    int idA = 0, idB = 30;
    if (valid) {
        const int base = b * 5;
        idA = (tA < 5) ? p.dt[base + tA]
            : (tA < 10) ? 15 + p.ds[base + tA - 5]
                        : 30 + p.sl[base + tA - 10];
        if (s < 7)
            idB = (tB < 5) ? p.dt[base + tB]
                : (tB < 10) ? 15 + p.ds[base + tB - 5]
                            : 30 + p.sl[base + tB - 10];
    }

    // x in out-pair form: x[pr] = {x_2pr, x_2pr+1}; emb rows are packed f32
    // so a u64 read gives exactly the pair.
    u64 xA[4], xB[4];
    {
        const u64 *ea = (const u64 *)&sw.emb[idA][0];
        u64x2 e01 = *(const u64x2 *)(ea), e23 = *(const u64x2 *)(ea + 2);
        xA[0] = e01.x; xA[1] = e01.y; xA[2] = e23.x; xA[3] = e23.y;
        const u64 *eb = (const u64 *)&sw.emb[idB][0];
        u64x2 f01 = *(const u64x2 *)(eb), f23 = *(const u64x2 *)(eb + 2);
        xB[0] = f01.x; xB[1] = f01.y; xB[2] = f23.x; xB[3] = f23.y;
    }

    u64 *kvg = &kvs[warp][g][0];
    u64 *rowA = kvg + tA * 8;
    u64 *rowB = kvg + tB * 8;
    u64 qA2[4], qB2[4], avA[4], avB[4];

    // ---- layer 0: qkv via table lookup ----
    {
        const u64 *ta = sw.t0[idA];
        u64x2 a0 = *(const u64x2 *)(ta), a1 = *(const u64x2 *)(ta + 2);
        qA2[0] = a0.x; qA2[1] = a0.y; qA2[2] = a1.x; qA2[3] = a1.y;
        *(u64x2 *)(rowA)     = *(const u64x2 *)(ta + 4);
        *(u64x2 *)(rowA + 2) = *(const u64x2 *)(ta + 6);
        *(u64x2 *)(rowA + 4) = *(const u64x2 *)(ta + 8);
        *(u64x2 *)(rowA + 6) = *(const u64x2 *)(ta + 10);
        const u64 *tb = sw.t0[idB];
        u64x2 b0 = *(const u64x2 *)(tb), b1 = *(const u64x2 *)(tb + 2);
        qB2[0] = b0.x; qB2[1] = b0.y; qB2[2] = b1.x; qB2[3] = b1.y;
        if (s < 7) {
            *(u64x2 *)(rowB)     = *(const u64x2 *)(tb + 4);
            *(u64x2 *)(rowB + 2) = *(const u64x2 *)(tb + 6);
            *(u64x2 *)(rowB + 4) = *(const u64x2 *)(tb + 8);
            *(u64x2 *)(rowB + 6) = *(const u64x2 *)(tb + 10);
        }
    }
    attn_dual(qA2, qB2, kvg, avA, avB);
    ff_dual(avA, avB, xA, xB, sw.Wo2[0], sw.bo2[0], sw.Wl2[0], sw.bl2[0]);

    // ---- layer 1: qkv via packed row pairs (weights amortized over 2 tokens) ----
    __syncwarp();   // layer-0 kv reads done before overwrite
    {
        u64 xdA[8], xdB[8];
        #pragma unroll
        for (int pr = 0; pr < 4; pr++) {
            float lo, hi;
            upk2(xA[pr], lo, hi); xdA[2 * pr] = pk2(lo, lo); xdA[2 * pr + 1] = pk2(hi, hi);
            upk2(xB[pr], lo, hi); xdB[2 * pr] = pk2(lo, lo); xdB[2 * pr + 1] = pk2(hi, hi);
        }
        u64 holdA = 0, holdB = 0;
        #pragma unroll
        for (int pr = 0; pr < 12; pr++) {
            const u64x2 *wp = (const u64x2 *)sw.Wq1[pr];
            u64x2 w01 = wp[0], w23 = wp[1], w45 = wp[2], w67 = wp[3];
            u64 bb = sw.bq1[pr];
            u64 a = ffma2(xdA[0], w01.x, bb);
            a = ffma2(xdA[1], w01.y, a); a = ffma2(xdA[2], w23.x, a);
            a = ffma2(xdA[3], w23.y, a); a = ffma2(xdA[4], w45.x, a);
            a = ffma2(xdA[5], w45.y, a); a = ffma2(xdA[6], w67.x, a);
            a = ffma2(xdA[7], w67.y, a);
            u64 c = ffma2(xdB[0], w01.x, bb);
            c = ffma2(xdB[1], w01.y, c); c = ffma2(xdB[2], w23.x, c);
            c = ffma2(xdB[3], w23.y, c); c = ffma2(xdB[4], w45.x, c);
            c = ffma2(xdB[5], w45.y, c); c = ffma2(xdB[6], w67.x, c);
            c = ffma2(xdB[7], w67.y, c);
            if (pr < 4) { qA2[pr] = a; qB2[pr] = c; }
            else if ((pr & 1) == 0) { holdA = a; holdB = c; }
            else {
                u64x2 st; st.x = holdA; st.y = a;
                *(u64x2 *)(rowA + (pr - 5)) = st;   // offsets 0,2,4,6
                if (s < 7) { st.x = holdB; st.y = c; *(u64x2 *)(rowB + (pr - 5)) = st; }
            }
        }
    }
    attn_dual(qA2, qB2, kvg, avA, avB);
    ff_dual(avA, avB, xA, xB, sw.Wo2[1], sw.bo2[1], sw.Wl2[1], sw.bl2[1]);

    // ---- mean pool over 15 tokens (8-lane groups), pair domain ----
    u64 xs[4];
    #pragma unroll
    for (int pr = 0; pr < 4; pr++) {
        u64 v = (s < 7) ? fadd2(xA[pr], xB[pr]) : xA[pr];
        v = fadd2(v, __shfl_xor_sync(0xffffffffu, v, 1));
        v = fadd2(v, __shfl_xor_sync(0xffffffffu, v, 2));
        v = fadd2(v, __shfl_xor_sync(0xffffffffu, v, 4));
        xs[pr] = fmul2(v, pk2(1.0f / 15.0f, 1.0f / 15.0f));
    }

    // ---- output projection: a = s, s+8, and (s<4) s+16 ----
    if (valid) {
        #pragma unroll
        for (int rep = 0; rep < 3; rep++) {
            const int a = s + 8 * rep;
            if (rep == 2 && s >= 4) break;
            const u64x2 *wp = (const u64x2 *)sw.Wout2[a];
            u64x2 w01 = wp[0], w23 = wp[1];
            u64 acc = fmul2(xs[0], w01.x);
            acc = ffma2(xs[1], w01.y, acc);
            acc = ffma2(xs[2], w23.x, acc);
            acc = ffma2(xs[3], w23.y, acc);
            float r0, r1; upk2(acc, r0, r1);
            p.out[b * 20 + a] = sw.bout[a] + r0 + r1;
        }
    }
}

extern "C" void kernel_launch(void* const* d_in, const int* in_sizes, int n_in,
                              void* d_out, int out_size) {
    Params p;
    p.dt = (const int *)d_in[0];
    p.ds = (const int *)d_in[1];
    p.sl = (const int *)d_in[2];
    p.emb_dice = (const float *)d_in[3];
    p.emb_star = (const float *)d_in[4];
    p.emb_btns = (const float *)d_in[5];

    int layer_base, wout_i, bout_i;
    if (in_sizes[6] == 160) { wout_i = 6; bout_i = 7; layer_base = 8; }
    else                    { layer_base = 6; wout_i = 18; bout_i = 19; }

    for (int l = 0; l < 2; l++) {
        int o = layer_base + 6 * l;
        p.Wqkv[l] = (const float *)d_in[o];
        p.bqkv[l] = (const float *)d_in[o + 1];
        p.Wo[l]   = (const float *)d_in[o + 2];
        p.bo[l]   = (const float *)d_in[o + 3];
        p.Wl[l]   = (const float *)d_in[o + 4];
        p.bl[l]   = (const float *)d_in[o + 5];
    }
    p.Wout = (const float *)d_in[wout_i];
    p.bout = (const float *)d_in[bout_i];
    p.out  = (float *)d_out;
    p.B    = in_sizes[0] / 5;

    prep_kernel<<<4, 256>>>(p);
    int blocks = (p.B + SPB - 1) / SPB;
    bot_kernel<<<blocks, TPB>>>(p);
}

// round 6
// speedup vs baseline: 1.5009x; 1.0823x over previous
#include <cuda_runtime.h>

// BetterBot round-6: R4 mapping (1 token/lane, 2 samples/warp) + layer-0
// attention fully table-ized: Wexp[id_k][id_q] = exp2(S * q(id_q).k(id_k)) per
// head, precomputed in prep. Layer-0 needs no q/k at runtime at all.

#define TPB 256
#define NW  8
#define SPB 16   // samples per block

typedef unsigned long long u64;
typedef ulonglong2 u64x2;

__device__ __forceinline__ u64 pk2(float lo, float hi) {
    u64 r; asm("mov.b64 %0,{%1,%2};" : "=l"(r) : "f"(lo), "f"(hi)); return r;
}
__device__ __forceinline__ void upk2(u64 v, float &lo, float &hi) {
    asm("mov.b64 {%0,%1},%2;" : "=f"(lo), "=f"(hi) : "l"(v));
}
__device__ __forceinline__ u64 ffma2(u64 a, u64 b, u64 c) {
    u64 d; asm("fma.rn.f32x2 %0,%1,%2,%3;" : "=l"(d) : "l"(a), "l"(b), "l"(c)); return d;
}
__device__ __forceinline__ u64 fmul2(u64 a, u64 b) {
    u64 d; asm("mul.rn.f32x2 %0,%1,%2;" : "=l"(d) : "l"(a), "l"(b)); return d;
}
__device__ __forceinline__ u64 fadd2(u64 a, u64 b) {
    u64 d; asm("add.rn.f32x2 %0,%1,%2;" : "=l"(d) : "l"(a), "l"(b)); return d;
}
__device__ __forceinline__ float ex2f(float x) {
    float r; asm("ex2.approx.f32 %0,%1;" : "=f"(r) : "f"(x)); return r;
}

struct Params {
    const int   *dt, *ds, *sl;
    const float *emb_dice, *emb_star, *emb_btns;
    const float *Wqkv[2], *bqkv[2], *Wo[2], *bo[2], *Wl[2], *bl[2];
    const float *Wout, *bout;
    float *out;
    int B;
};

struct __align__(16) GW {
    u64 Wexp[32][33];    // [id_k][id_q] packed per-head exp'd scores; 33 stride de-banks
    u64 t0v[32][4];      // layer-0 v pairs {v_h0[i], v_h1[i]}
    u64 embp[32][6];     // x pairs (8 floats used; 48B stride, 16B aligned)
    u64 Wq1[12][8];      // layer-1 Wqkv row pairs (g*8+r, g*8+r+4); q rows pre-scaled
    u64 bq1[12];
    u64 Wo2[2][4][8];    // row pairs (2p, 2p+1)
    u64 bo2[2][4];
    u64 Wl2[2][4][8];
    u64 bl2[2][4];
    u64 Wout2[20][4];
    float bout[20];
    float pad[4];
};
__device__ GW g_w;
__device__ u64 g_q0[32][4];   // layer-0 q pairs, S-prescaled (prep only)
__device__ u64 g_k0[32][4];   // layer-0 k pairs (prep only)

__global__ void prep1_kernel(Params p) {
    int i = blockIdx.x * blockDim.x + threadIdx.x;
    const float S = 0.72134752f;   // 0.5 * log2(e)
    if (i < 384) {
        int id = i / 12, pp = i % 12;
        int gg = pp >> 2, r = pp & 3;
        int r0 = gg * 8 + r, r1 = r0 + 4;
        const float *e = (id < 15) ? p.emb_dice + id * 8
                        : (id < 30) ? p.emb_star + (id - 15) * 8
                                    : p.emb_btns + (id - 30) * 8;
        const float *w0 = p.Wqkv[0] + r0 * 8;
        const float *w1 = p.Wqkv[0] + r1 * 8;
        u64 acc = pk2(p.bqkv[0][r0], p.bqkv[0][r1]);
        #pragma unroll
        for (int j = 0; j < 8; j++)
            acc = ffma2(pk2(e[j], e[j]), pk2(w0[j], w1[j]), acc);
        if (pp < 4)      g_q0[id][pp]     = fmul2(acc, pk2(S, S));
        else if (pp < 8) g_k0[id][pp - 4] = acc;
        else             g_w.t0v[id][pp - 8] = acc;
    } else if (i < 480) {
        int k = i - 384; int pp = k >> 3, j = k & 7;
        int gg = pp >> 2, r = pp & 3, r0 = gg * 8 + r, r1 = r0 + 4;
        u64 w = pk2(p.Wqkv[1][r0 * 8 + j], p.Wqkv[1][r1 * 8 + j]);
        if (pp < 4) w = fmul2(w, pk2(S, S));
        g_w.Wq1[pp][j] = w;
    } else if (i < 492) {
        int pp = i - 480; int gg = pp >> 2, r = pp & 3, r0 = gg * 8 + r;
        u64 w = pk2(p.bqkv[1][r0], p.bqkv[1][r0 + 4]);
        if (pp < 4) w = fmul2(w, pk2(S, S));
        g_w.bq1[pp] = w;
    } else if (i < 556) {
        int k = i - 492; int l = k >> 5, pr = (k >> 3) & 3, j = k & 7;
        g_w.Wo2[l][pr][j] = pk2(p.Wo[l][2 * pr * 8 + j], p.Wo[l][(2 * pr + 1) * 8 + j]);
    } else if (i < 564) {
        int k = i - 556; int l = k >> 2, pr = k & 3;
        g_w.bo2[l][pr] = pk2(p.bo[l][2 * pr], p.bo[l][2 * pr + 1]);
    } else if (i < 628) {
        int k = i - 564; int l = k >> 5, pr = (k >> 3) & 3, j = k & 7;
        g_w.Wl2[l][pr][j] = pk2(p.Wl[l][2 * pr * 8 + j], p.Wl[l][(2 * pr + 1) * 8 + j]);
    } else if (i < 636) {
        int k = i - 628; int l = k >> 2, pr = k & 3;
        g_w.bl2[l][pr] = pk2(p.bl[l][2 * pr], p.bl[l][2 * pr + 1]);
    } else if (i < 716) {
        int k = i - 636; int a = k >> 2, j = k & 3;
        g_w.Wout2[a][j] = pk2(p.Wout[a * 8 + 2 * j], p.Wout[a * 8 + 2 * j + 1]);
    } else if (i < 736) {
        g_w.bout[i - 716] = p.bout[i - 716];
    } else if (i < 992) {
        int k = i - 736; int id = k >> 3, j = k & 7;
        const float *e = (id < 15) ? p.emb_dice + id * 8
                        : (id < 30) ? p.emb_star + (id - 15) * 8
                                    : p.emb_btns + (id - 30) * 8;
        ((float *)g_w.embp[id])[j] = e[j];
    }
}

__global__ void prep2_kernel() {
    int i = blockIdx.x * blockDim.x + threadIdx.x;
    if (i >= 1024) return;
    int a = i >> 5, b = i & 31;           // a = query id, b = key id
    u64 s2 = 0;
    #pragma unroll
    for (int j = 0; j < 4; j++)
        s2 = ffma2(g_q0[a][j], g_k0[b][j], s2);
    float s0, s1; upk2(s2, s0, s1);
    g_w.Wexp[b][a] = pk2(ex2f(s0), ex2f(s1));
}

// o-proj + residual + MLP + residual; x float[8] updated in place
__device__ __forceinline__ void ff1(
    const float *o, float *x,
    const u64 (*wo2)[8], const u64 *bo2,
    const u64 (*wl2)[8], const u64 *bl2)
{
    u64 od[8];
    #pragma unroll
    for (int i = 0; i < 8; i++) od[i] = pk2(o[i], o[i]);
    float xo[8];
    #pragma unroll
    for (int pr = 0; pr < 4; pr++) {
        const u64x2 *wp = (const u64x2 *)wo2[pr];
        u64x2 w01 = wp[0], w23 = wp[1], w45 = wp[2], w67 = wp[3];
        u64 acc = ffma2(od[0], w01.x, bo2[pr]);
        acc = ffma2(od[1], w01.y, acc); acc = ffma2(od[2], w23.x, acc);
        acc = ffma2(od[3], w23.y, acc); acc = ffma2(od[4], w45.x, acc);
        acc = ffma2(od[5], w45.y, acc); acc = ffma2(od[6], w67.x, acc);
        acc = ffma2(od[7], w67.y, acc);
        float r0, r1; upk2(acc, r0, r1);
        xo[2 * pr] = x[2 * pr] + r0; xo[2 * pr + 1] = x[2 * pr + 1] + r1;
    }
    u64 xd[8];
    #pragma unroll
    for (int i = 0; i < 8; i++) xd[i] = pk2(xo[i], xo[i]);
    #pragma unroll
    for (int pr = 0; pr < 4; pr++) {
        const u64x2 *wp = (const u64x2 *)wl2[pr];
        u64x2 w01 = wp[0], w23 = wp[1], w45 = wp[2], w67 = wp[3];
        u64 acc = ffma2(xd[0], w01.x, bl2[pr]);
        acc = ffma2(xd[1], w01.y, acc); acc = ffma2(xd[2], w23.x, acc);
        acc = ffma2(xd[3], w23.y, acc); acc = ffma2(xd[4], w45.x, acc);
        acc = ffma2(xd[5], w45.y, acc); acc = ffma2(xd[6], w67.x, acc);
        acc = ffma2(xd[7], w67.y, acc);
        float r0, r1; upk2(acc, r0, r1);
        x[2 * pr]     = xo[2 * pr]     + fmaxf(r0, 0.f);
        x[2 * pr + 1] = xo[2 * pr + 1] + fmaxf(r1, 0.f);
    }
}

__global__ void __launch_bounds__(TPB, 4) bot_kernel(Params p) {
    __shared__ __align__(16) GW sw;                       // 13760 B
    // layer-1 kv: [warp][half][168 u64]; half stride 1344 B (%128==64 ->
    // conflict-free vs other half). token row = 10 u64: k01,k23,v01,v23,pad2.
    __shared__ __align__(16) u64 kvs[NW][2][168];         // 21504 B
    __shared__ __align__(16) unsigned char idsb[NW][2][16];

    const int tid = threadIdx.x;
    {
        const u64x2 *src = (const u64x2 *)&g_w;
        u64x2 *dst = (u64x2 *)&sw;
        #pragma unroll
        for (int k = 0; k < 4; k++) {
            int i = tid + k * TPB;
            if (i < (int)(sizeof(GW) / 16)) dst[i] = src[i];
        }
    }
    __syncthreads();

    const int warp = tid >> 5, lane = tid & 31;
    const int half = lane >> 4, s = lane & 15;
    const int b = blockIdx.x * SPB + warp * 2 + half;
    const bool tok = (s < 15);

    int id = 0;   // lane 15 dummy (harmless: slot 15 never read in attn loops)
    if (tok) {
        const int base = b * 5;
        id = (s < 5) ? p.dt[base + s]
           : (s < 10) ? 15 + p.ds[base + s - 5]
                      : 30 + p.sl[base + s - 10];
    }
    idsb[warp][half][s] = (unsigned char)id;
    __syncwarp();
    const uint4 idw = *(const uint4 *)&idsb[warp][half][0];

    float x[8];
    {
        const u64x2 *e = (const u64x2 *)&sw.embp[id][0];
        u64x2 e01 = e[0], e23 = e[1];
        upk2(e01.x, x[0], x[1]); upk2(e01.y, x[2], x[3]);
        upk2(e23.x, x[4], x[5]); upk2(e23.y, x[6], x[7]);
    }

    // ---- layer 0 attention: pure table reads, no q/k ----
    {
        u64 sum2 = 0, av0 = 0, av1 = 0, av2 = 0, av3 = 0;
        #pragma unroll
        for (int t = 0; t < 15; t++) {
            unsigned idt = ((&idw.x)[t >> 2] >> ((t & 3) * 8)) & 0xFF;
            const u64 *wrow = (const u64 *)((const char *)sw.Wexp + idt * 264);
            u64 w = wrow[id];                       // LDS.64, col spread by id
            const u64x2 *vp = (const u64x2 *)sw.t0v[idt];
            u64x2 v01 = vp[0], v23 = vp[1];         // broadcast
            sum2 = fadd2(sum2, w);
            av0 = ffma2(w, v01.x, av0); av1 = ffma2(w, v01.y, av1);
            av2 = ffma2(w, v23.x, av2); av3 = ffma2(w, v23.y, av3);
        }
        float s0, s1; upk2(sum2, s0, s1);
        u64 inv = pk2(__fdividef(1.f, s0), __fdividef(1.f, s1));
        float o[8];
        { u64 t = fmul2(av0, inv); upk2(t, o[0], o[4]); }
        { u64 t = fmul2(av1, inv); upk2(t, o[1], o[5]); }
        { u64 t = fmul2(av2, inv); upk2(t, o[2], o[6]); }
        { u64 t = fmul2(av3, inv); upk2(t, o[3], o[7]); }
        ff1(o, x, sw.Wo2[0], sw.bo2[0], sw.Wl2[0], sw.bl2[0]);
    }

    // ---- layer 1: qkv gemv -> kv exchange -> attention ----
    u64 *kvh = &kvs[warp][half][0];
    u64 *row = kvh + s * 10;
    u64 q2[4];
    {
        u64 xd[8];
        #pragma unroll
        for (int i = 0; i < 8; i++) xd[i] = pk2(x[i], x[i]);
        u64 hold = 0;
        #pragma unroll
        for (int pr = 0; pr < 12; pr++) {
            const u64x2 *wp = (const u64x2 *)sw.Wq1[pr];
            u64x2 w01 = wp[0], w23 = wp[1], w45 = wp[2], w67 = wp[3];
            u64 a = ffma2(xd[0], w01.x, sw.bq1[pr]);
            a = ffma2(xd[1], w01.y, a); a = ffma2(xd[2], w23.x, a);
            a = ffma2(xd[3], w23.y, a); a = ffma2(xd[4], w45.x, a);
            a = ffma2(xd[5], w45.y, a); a = ffma2(xd[6], w67.x, a);
            a = ffma2(xd[7], w67.y, a);
            if (pr < 4) q2[pr] = a;
            else if ((pr & 1) == 0) hold = a;
            else if (tok) {
                u64x2 st; st.x = hold; st.y = a;
                *(u64x2 *)(row + (pr - 5)) = st;   // offsets 0,2,4,6
            }
        }
    }
    __syncwarp();   // kv writes -> kv reads
    {
        u64 sum2 = 0, av0 = 0, av1 = 0, av2 = 0, av3 = 0;
        #pragma unroll
        for (int t = 0; t < 15; t++) {
            const u64 *r = kvh + t * 10;
            u64x2 k01 = *(const u64x2 *)(r);
            u64x2 k23 = *(const u64x2 *)(r + 2);
            u64 s2 = fmul2(q2[0], k01.x);
            s2 = ffma2(q2[1], k01.y, s2);
            s2 = ffma2(q2[2], k23.x, s2);
            s2 = ffma2(q2[3], k23.y, s2);
            float f0, f1; upk2(s2, f0, f1);
            u64 w = pk2(ex2f(f0), ex2f(f1));
            u64x2 v01 = *(const u64x2 *)(r + 4);
            u64x2 v23 = *(const u64x2 *)(r + 6);
            sum2 = fadd2(sum2, w);
            av0 = ffma2(w, v01.x, av0); av1 = ffma2(w, v01.y, av1);
            av2 = ffma2(w, v23.x, av2); av3 = ffma2(w, v23.y, av3);
        }
        float s0, s1; upk2(sum2, s0, s1);
        u64 inv = pk2(__fdividef(1.f, s0), __fdividef(1.f, s1));
        float o[8];
        { u64 t = fmul2(av0, inv); upk2(t, o[0], o[4]); }
        { u64 t = fmul2(av1, inv); upk2(t, o[1], o[5]); }
        { u64 t = fmul2(av2, inv); upk2(t, o[2], o[6]); }
        { u64 t = fmul2(av3, inv); upk2(t, o[3], o[7]); }
        ff1(o, x, sw.Wo2[1], sw.bo2[1], sw.Wl2[1], sw.bl2[1]);
    }

    // ---- mean pool over 15 tokens (16-lane groups) ----
    #pragma unroll
    for (int j = 0; j < 8; j++) {
        float v = tok ? x[j] : 0.f;
        v += __shfl_xor_sync(0xffffffffu, v, 1);
        v += __shfl_xor_sync(0xffffffffu, v, 2);
        v += __shfl_xor_sync(0xffffffffu, v, 4);
        v += __shfl_xor_sync(0xffffffffu, v, 8);
        x[j] = v * (1.0f / 15.0f);
    }

    // ---- output projection ----
    if (b < p.B) {
        u64 xq[4];
        #pragma unroll
        for (int i = 0; i < 4; i++) xq[i] = pk2(x[2 * i], x[2 * i + 1]);
        {
            const u64x2 *wp = (const u64x2 *)sw.Wout2[s];
            u64x2 w01 = wp[0], w23 = wp[1];
            u64 acc = fmul2(xq[0], w01.x);
            acc = ffma2(xq[1], w01.y, acc);
            acc = ffma2(xq[2], w23.x, acc);
            acc = ffma2(xq[3], w23.y, acc);
            float r0, r1; upk2(acc, r0, r1);
            p.out[b * 20 + s] = sw.bout[s] + r0 + r1;
        }
        if (s < 4) {
            const int a = s + 16;
            const u64x2 *wp = (const u64x2 *)sw.Wout2[a];
            u64x2 w01 = wp[0], w23 = wp[1];
            u64 acc = fmul2(xq[0], w01.x);
            acc = ffma2(xq[1], w01.y, acc);
            acc = ffma2(xq[2], w23.x, acc);
            acc = ffma2(xq[3], w23.y, acc);
            float r0, r1; upk2(acc, r0, r1);
            p.out[b * 20 + a] = sw.bout[a] + r0 + r1;
        }
    }
}

extern "C" void kernel_launch(void* const* d_in, const int* in_sizes, int n_in,
                              void* d_out, int out_size) {
    Params p;
    p.dt = (const int *)d_in[0];
    p.ds = (const int *)d_in[1];
    p.sl = (const int *)d_in[2];
    p.emb_dice = (const float *)d_in[3];
    p.emb_star = (const float *)d_in[4];
    p.emb_btns = (const float *)d_in[5];

    int layer_base, wout_i, bout_i;
    if (in_sizes[6] == 160) { wout_i = 6; bout_i = 7; layer_base = 8; }
    else                    { layer_base = 6; wout_i = 18; bout_i = 19; }

    for (int l = 0; l < 2; l++) {
        int o = layer_base + 6 * l;
        p.Wqkv[l] = (const float *)d_in[o];
        p.bqkv[l] = (const float *)d_in[o + 1];
        p.Wo[l]   = (const float *)d_in[o + 2];
        p.bo[l]   = (const float *)d_in[o + 3];
        p.Wl[l]   = (const float *)d_in[o + 4];
        p.bl[l]   = (const float *)d_in[o + 5];
    }
    p.Wout = (const float *)d_in[wout_i];
    p.bout = (const float *)d_in[bout_i];
    p.out  = (float *)d_out;
    p.B    = in_sizes[0] / 5;

    prep1_kernel<<<4, 256>>>(p);
    prep2_kernel<<<4, 256>>>();
    int blocks = (p.B + SPB - 1) / SPB;
    bot_kernel<<<blocks, TPB>>>(p);
}